// round 2
// baseline (speedup 1.0000x reference)
#include <cuda_runtime.h>
#include <math.h>

// Problem constants (B=4, S=2048, D_IN=1024, D_OUT=1024, E=8, K=2)
#define BTOK   8192
#define DIN    1024
#define DOUT   1024
#define NE     8
#define NROW   24        // 8 gate rows + 16 expert rows (e, o in {0,1})
#define NPAIR  12        // NROW/2 adjacent-row pairs
#define TM     32        // tokens per block
#define TK     128       // K chunk
#define THREADS 192      // 32 tokens * 6 output-groups (4 outputs each)

#define XS_STRIDE 132    // 128 + 4 pad
#define WP_STRIDE 26     // floats per k-slice: 12 float2 + 1 float2 pad (8B-aligned)

__device__ __forceinline__ unsigned long long pack2(float a, float b) {
    unsigned long long r;
    asm("mov.b64 %0, {%1, %2};" : "=l"(r) : "f"(a), "f"(b));
    return r;
}
__device__ __forceinline__ unsigned long long fma2(unsigned long long a,
                                                   unsigned long long b,
                                                   unsigned long long c) {
    unsigned long long d;
    asm("fma.rn.f32x2 %0, %1, %2, %3;" : "=l"(d) : "l"(a), "l"(b), "l"(c));
    return d;
}
__device__ __forceinline__ void unpack2(unsigned long long v, float& lo, float& hi) {
    asm("mov.b64 {%0, %1}, %2;" : "=f"(lo), "=f"(hi) : "l"(v));
}

__global__ __launch_bounds__(THREADS)
void moe_fused_kernel(const float* __restrict__ x,
                      const float* __restrict__ gate_w,
                      const float* __restrict__ gate_b,
                      const float* __restrict__ ebias,
                      const float* __restrict__ expert_w,
                      const float* __restrict__ expert_b,
                      float* __restrict__ out,
                      float* __restrict__ idx_out)
{
    __shared__ float xs[TM][XS_STRIDE];          // 16896 B  (also reused as Pbuf)
    __shared__ float ws2[TK * WP_STRIDE];        // 13312 B  k-major paired weights
    __shared__ float wtok[TM];
    __shared__ const float* rowsrc[NROW];

    const int tid  = threadIdx.x;
    const int tok0 = blockIdx.x * TM;

    // thread tile: tg = token in [0,32), og = output group in [0,6) -> 4 outputs
    const int tg = tid / 6;
    const int og = tid - tg * 6;

    if (tid < NROW) {
        rowsrc[tid] = (tid < NE)
            ? (gate_w + (size_t)tid * DIN)
            : (expert_w + ((size_t)(((tid - NE) >> 1) * DOUT + ((tid - NE) & 1))) * DIN);
    }

    unsigned long long acc0 = 0ULL, acc1 = 0ULL;   // float2 zeros

    for (int k0 = 0; k0 < DIN; k0 += TK) {
        __syncthreads();   // prior compute done; rowsrc visible on first iter

        // ---- load x chunk: 1024 float4 across 192 threads (coalesced) ----
        for (int i = tid; i < (TM * TK) / 4; i += THREADS) {
            int m  = i >> 5;             // token row
            int f4 = (i & 31) << 2;      // float offset in 128-float row
            float4 v = *(const float4*)(x + (size_t)(tok0 + m) * DIN + k0 + f4);
            *(float4*)&xs[m][f4] = v;
        }

        // ---- load weights k-major as adjacent-row pairs ----
        // ws2[kk*26 + pair*2 + comp] = row[2*pair+comp][k0+kk]
        #pragma unroll
        for (int i = 0; i < (NROW * TK) / THREADS; i++) {    // 16 iters
            int t   = tid + i * THREADS;
            int row = t >> 7;            // TK = 128
            int kk  = t & 127;
            ws2[kk * WP_STRIDE + (row >> 1) * 2 + (row & 1)] = rowsrc[row][k0 + kk];
        }

        __syncthreads();

        // ---- inner product: 1 token x 4 outputs via packed f32x2 FMA ----
        const float* xr = &xs[tg][0];
        const float* wb = &ws2[og * 4];
        #pragma unroll 16
        for (int kk = 0; kk < TK; kk++) {
            float xv = xr[kk];
            unsigned long long xd = pack2(xv, xv);
            unsigned long long w0 = *(const unsigned long long*)(wb + kk * WP_STRIDE);
            unsigned long long w1 = *(const unsigned long long*)(wb + kk * WP_STRIDE + 2);
            acc0 = fma2(xd, w0, acc0);
            acc1 = fma2(xd, w1, acc1);
        }
    }

    // ---- stash P[32][24] into xs overlay (stride 25) ----
    __syncthreads();
    float* Pbuf = &xs[0][0];
    {
        float p0, p1, p2, p3;
        unpack2(acc0, p0, p1);
        unpack2(acc1, p2, p3);
        float* Pm = Pbuf + tg * 25 + og * 4;
        Pm[0] = p0; Pm[1] = p1; Pm[2] = p2; Pm[3] = p3;
    }
    __syncthreads();

    // ---- per-token top-2 + sigmoid + combine (threads 0..31) ----
    if (tid < TM) {
        const float* Pm = Pbuf + tid * 25;
        float l[NE];
        #pragma unroll
        for (int e = 0; e < NE; e++)
            l[e] = Pm[e] + gate_b[e] + ebias[e];

        int e0 = 0; float b0 = l[0];
        #pragma unroll
        for (int e = 1; e < NE; e++)
            if (l[e] > b0) { b0 = l[e]; e0 = e; }
        int e1 = -1; float b1 = -INFINITY;
        #pragma unroll
        for (int e = 0; e < NE; e++) {
            if (e == e0) continue;
            if (l[e] > b1) { b1 = l[e]; e1 = e; }
        }

        float p0 = 1.f / (1.f + expf(-b0));
        float p1 = 1.f / (1.f + expf(-b1));
        float inv = 1.f / (p0 + p1);

        float v0 = Pm[NE + e0 * 2 + 0] + expert_b[(size_t)e0 * DOUT + 0];
        float v1 = Pm[NE + e1 * 2 + 1] + expert_b[(size_t)e1 * DOUT + 1];
        wtok[tid] = (v0 * p0 + v1 * p1) * inv;

        if (idx_out) {
            idx_out[(size_t)(tok0 + tid) * 2 + 0] = (float)e0;
            idx_out[(size_t)(tok0 + tid) * 2 + 1] = (float)e1;
        }
    }
    __syncthreads();

    // ---- broadcast write: each token -> 1024 identical floats ----
    // 192 threads cover 768 floats/pass; 2 passes per token (2nd partial).
    const int fo = tid << 2;
    #pragma unroll 4
    for (int m = 0; m < TM; m++) {
        float v = wtok[m];
        float4 v4 = make_float4(v, v, v, v);
        float* base = out + (size_t)(tok0 + m) * DOUT;
        *(float4*)(base + fo) = v4;
        if (tid < (DOUT - THREADS * 4) / 4)              // 64 threads
            *(float4*)(base + THREADS * 4 + fo) = v4;
    }
}

extern "C" void kernel_launch(void* const* d_in, const int* in_sizes, int n_in,
                              void* d_out, int out_size)
{
    const float* x        = (const float*)d_in[0];
    const float* gate_w   = (const float*)d_in[1];
    const float* gate_b   = (const float*)d_in[2];
    const float* ebias    = (const float*)d_in[3];
    const float* expert_w = (const float*)d_in[4];
    const float* expert_b = (const float*)d_in[5];
    float* out = (float*)d_out;

    float* idx_out = nullptr;
    long long base = (long long)BTOK * DOUT;
    if ((long long)out_size >= base + (long long)BTOK * 2)
        idx_out = out + base;

    moe_fused_kernel<<<BTOK / TM, THREADS>>>(x, gate_w, gate_b, ebias,
                                             expert_w, expert_b, out, idx_out);
}

// round 3
// speedup vs baseline: 2.0549x; 2.0549x over previous
#include <cuda_runtime.h>
#include <math.h>

// Problem constants (B=4, S=2048, D_IN=1024, D_OUT=1024, E=8, K=2)
#define BTOK    8192
#define DIN     1024
#define DOUT    1024
#define NE      8
#define NROW    24       // 8 gate rows + 16 expert rows (e, o in {0,1})
#define TM      64       // tokens per GEMM block
#define TK      128      // k sub-chunk
#define SPLITK  4
#define KSPAN   (DIN / SPLITK)       // 256 k per block
#define THREADS 256

#define XS_STRIDE 132    // conflict-free for LDS.128 (banks 8*tg)
#define WS_STRIDE 132    // conflict-free for LDS.128 (banks 12*og+4*r, disjoint)

// Partial P results: [token][split][24] -> 96 contiguous floats per token
__device__ float g_scratch[BTOK * SPLITK * NROW];   // 3 MB

// ---------------------------------------------------------------------------
// Kernel 1: split-K skinny GEMM  P_partial = x @ Wcat^T
// ---------------------------------------------------------------------------
__global__ __launch_bounds__(THREADS)
void moe_gemm_kernel(const float* __restrict__ x,
                     const float* __restrict__ gate_w,
                     const float* __restrict__ expert_w)
{
    __shared__ float xs[TM][XS_STRIDE];      // 33792 B
    __shared__ float ws[NROW][WS_STRIDE];    // 12672 B
    __shared__ const float* rowsrc[NROW];

    const int tid   = threadIdx.x;
    const int split = blockIdx.x & (SPLITK - 1);
    const int tb    = blockIdx.x >> 2;
    const int tok0  = tb * TM;
    const int kbase = split * KSPAN;

    // thread tile: og in [0,8) -> 3 outputs; tg in [0,32) -> 2 tokens
    const int og = tid & 7;
    const int tg = tid >> 3;

    if (tid < NROW) {
        rowsrc[tid] = (tid < NE)
            ? (gate_w + (size_t)tid * DIN)
            : (expert_w + ((size_t)(((tid - NE) >> 1) * DOUT + ((tid - NE) & 1))) * DIN);
    }

    float acc[2][3];
    #pragma unroll
    for (int t = 0; t < 2; t++)
        #pragma unroll
        for (int n = 0; n < 3; n++) acc[t][n] = 0.f;

    #pragma unroll
    for (int c = 0; c < KSPAN / TK; c++) {            // 2 chunks
        const int k0 = kbase + c * TK;
        __syncthreads();

        // ---- x chunk: 64 tokens x 128 floats = 2048 float4 (coalesced) ----
        #pragma unroll
        for (int r = 0; r < (TM * TK) / (4 * THREADS); r++) {   // 8
            int i  = tid + r * THREADS;
            int m  = i >> 5;
            int f4 = (i & 31) << 2;
            float4 v = *(const float4*)(x + (size_t)(tok0 + m) * DIN + k0 + f4);
            *(float4*)&xs[m][f4] = v;
        }

        // ---- weight chunk: 24 rows x 128 floats = 768 float4 ----
        #pragma unroll
        for (int r = 0; r < (NROW * TK) / (4 * THREADS); r++) { // 3
            int i   = tid + r * THREADS;
            int row = i >> 5;
            int f4  = (i & 31) << 2;
            float4 v = *(const float4*)(rowsrc[row] + k0 + f4);
            *(float4*)&ws[row][f4] = v;
        }

        __syncthreads();

        // ---- inner product, float4-vectorized: 2 tokens x 3 outputs ----
        const float* xr0 = &xs[tg * 2 + 0][0];
        const float* xr1 = &xs[tg * 2 + 1][0];
        const float* wr0 = &ws[og * 3 + 0][0];
        const float* wr1 = &ws[og * 3 + 1][0];
        const float* wr2 = &ws[og * 3 + 2][0];
        #pragma unroll 8
        for (int kk = 0; kk < TK; kk += 4) {
            float4 xa = *(const float4*)(xr0 + kk);
            float4 xb = *(const float4*)(xr1 + kk);
            float4 w0 = *(const float4*)(wr0 + kk);
            float4 w1 = *(const float4*)(wr1 + kk);
            float4 w2 = *(const float4*)(wr2 + kk);
            acc[0][0] = fmaf(xa.x, w0.x, acc[0][0]);
            acc[0][0] = fmaf(xa.y, w0.y, acc[0][0]);
            acc[0][0] = fmaf(xa.z, w0.z, acc[0][0]);
            acc[0][0] = fmaf(xa.w, w0.w, acc[0][0]);
            acc[0][1] = fmaf(xa.x, w1.x, acc[0][1]);
            acc[0][1] = fmaf(xa.y, w1.y, acc[0][1]);
            acc[0][1] = fmaf(xa.z, w1.z, acc[0][1]);
            acc[0][1] = fmaf(xa.w, w1.w, acc[0][1]);
            acc[0][2] = fmaf(xa.x, w2.x, acc[0][2]);
            acc[0][2] = fmaf(xa.y, w2.y, acc[0][2]);
            acc[0][2] = fmaf(xa.z, w2.z, acc[0][2]);
            acc[0][2] = fmaf(xa.w, w2.w, acc[0][2]);
            acc[1][0] = fmaf(xb.x, w0.x, acc[1][0]);
            acc[1][0] = fmaf(xb.y, w0.y, acc[1][0]);
            acc[1][0] = fmaf(xb.z, w0.z, acc[1][0]);
            acc[1][0] = fmaf(xb.w, w0.w, acc[1][0]);
            acc[1][1] = fmaf(xb.x, w1.x, acc[1][1]);
            acc[1][1] = fmaf(xb.y, w1.y, acc[1][1]);
            acc[1][1] = fmaf(xb.z, w1.z, acc[1][1]);
            acc[1][1] = fmaf(xb.w, w1.w, acc[1][1]);
            acc[1][2] = fmaf(xb.x, w2.x, acc[1][2]);
            acc[1][2] = fmaf(xb.y, w2.y, acc[1][2]);
            acc[1][2] = fmaf(xb.z, w2.z, acc[1][2]);
            acc[1][2] = fmaf(xb.w, w2.w, acc[1][2]);
        }
    }

    // ---- write partials: scratch[token][split][24] ----
    #pragma unroll
    for (int t = 0; t < 2; t++) {
        int token = tok0 + tg * 2 + t;
        float* dst = g_scratch + ((size_t)token * SPLITK + split) * NROW + og * 3;
        dst[0] = acc[t][0];
        dst[1] = acc[t][1];
        dst[2] = acc[t][2];
    }
}

// ---------------------------------------------------------------------------
// Kernel 2: reduce partials + gating epilogue + broadcast write
// ---------------------------------------------------------------------------
#define TOKB 32

__global__ __launch_bounds__(THREADS)
void moe_epilogue_kernel(const float* __restrict__ gate_b,
                         const float* __restrict__ ebias,
                         const float* __restrict__ expert_b,
                         float* __restrict__ out,
                         float* __restrict__ idx_out)
{
    __shared__ float wtok[TOKB];
    const int tid  = threadIdx.x;
    const int tok0 = blockIdx.x * TOKB;

    if (tid < TOKB) {
        const int token = tok0 + tid;
        const float* src = g_scratch + (size_t)token * SPLITK * NROW;

        float P[NROW];
        #pragma unroll
        for (int r = 0; r < NROW; r++) P[r] = 0.f;
        #pragma unroll
        for (int s = 0; s < SPLITK; s++) {
            #pragma unroll
            for (int r4 = 0; r4 < NROW / 4; r4++) {
                float4 v = *(const float4*)(src + s * NROW + r4 * 4);
                P[r4 * 4 + 0] += v.x;
                P[r4 * 4 + 1] += v.y;
                P[r4 * 4 + 2] += v.z;
                P[r4 * 4 + 3] += v.w;
            }
        }

        float l[NE];
        #pragma unroll
        for (int e = 0; e < NE; e++)
            l[e] = P[e] + gate_b[e] + ebias[e];

        int e0 = 0; float b0 = l[0];
        #pragma unroll
        for (int e = 1; e < NE; e++)
            if (l[e] > b0) { b0 = l[e]; e0 = e; }
        int e1 = -1; float b1 = -INFINITY;
        #pragma unroll
        for (int e = 0; e < NE; e++) {
            if (e == e0) continue;
            if (l[e] > b1) { b1 = l[e]; e1 = e; }
        }

        float p0 = 1.f / (1.f + expf(-b0));
        float p1 = 1.f / (1.f + expf(-b1));
        float inv = 1.f / (p0 + p1);

        float v0 = P[NE + e0 * 2 + 0] + expert_b[(size_t)e0 * DOUT + 0];
        float v1 = P[NE + e1 * 2 + 1] + expert_b[(size_t)e1 * DOUT + 1];
        wtok[tid] = (v0 * p0 + v1 * p1) * inv;

        if (idx_out) {
            idx_out[(size_t)token * 2 + 0] = (float)e0;
            idx_out[(size_t)token * 2 + 1] = (float)e1;
        }
    }
    __syncthreads();

    // broadcast write: 256 threads x float4 = 1024 floats per token
    const int fo = tid << 2;
    #pragma unroll 4
    for (int m = 0; m < TOKB; m++) {
        float v = wtok[m];
        float4 v4 = make_float4(v, v, v, v);
        *(float4*)(out + (size_t)(tok0 + m) * DOUT + fo) = v4;
    }
}

extern "C" void kernel_launch(void* const* d_in, const int* in_sizes, int n_in,
                              void* d_out, int out_size)
{
    const float* x        = (const float*)d_in[0];
    const float* gate_w   = (const float*)d_in[1];
    const float* gate_b   = (const float*)d_in[2];
    const float* ebias    = (const float*)d_in[3];
    const float* expert_w = (const float*)d_in[4];
    const float* expert_b = (const float*)d_in[5];
    float* out = (float*)d_out;

    float* idx_out = nullptr;
    long long base = (long long)BTOK * DOUT;
    if ((long long)out_size >= base + (long long)BTOK * 2)
        idx_out = out + base;

    moe_gemm_kernel<<<(BTOK / TM) * SPLITK, THREADS>>>(x, gate_w, expert_w);
    moe_epilogue_kernel<<<BTOK / TOKB, THREADS>>>(gate_b, ebias, expert_b,
                                                  out, idx_out);
}